// round 11
// baseline (speedup 1.0000x reference)
#include <cuda_runtime.h>
#include <cuda_bf16.h>
#include <cstdint>

// ---------------------------------------------------------------------------
// HeteroGraphSAGE forward on GB300 — round 5:
//  - mma.sync bf16 split-3 GEMM, now software-pipelined (reg prefetch of next
//    k-chunk + double-buffered smem tiles, one barrier per chunk).
//  - final layer scatters directly into d_out (agg2 buffers/memsets removed).
// ---------------------------------------------------------------------------

#define NU   100000
#define NI   200000
#define NE   600000
#define DIN  128
#define DHID 256
#define DOUT 128

// scratch layout (floats)
#define OFF_XI      0LL
#define OFF_AGG_I   25600000LL
#define OFF_AGG_U   51200000LL
#define OFF_H_I     64000000LL
#define OFF_H_U     115200000LL
#define OFF_Y_U2    140800000LL
#define OFF_Y_I2    153600000LL
#define SCRATCH_SZ  179200000LL

__device__ float g_scratch[SCRATCH_SZ];

// ---------------------------------------------------------------------------
// helpers
// ---------------------------------------------------------------------------
__device__ __forceinline__ uint32_t smem_u32(const void* p) {
    uint32_t a;
    asm("{ .reg .u64 t; cvta.to.shared.u64 t, %1; cvt.u32.u64 %0, t; }"
        : "=r"(a) : "l"(p));
    return a;
}

__device__ __forceinline__ void ldsm4(uint32_t* r, uint32_t addr) {
    asm volatile("ldmatrix.sync.aligned.m8n8.x4.shared.b16 {%0,%1,%2,%3}, [%4];"
                 : "=r"(r[0]), "=r"(r[1]), "=r"(r[2]), "=r"(r[3])
                 : "r"(addr));
}

__device__ __forceinline__ void mma_bf16(float* c, const uint32_t* a,
                                         const uint32_t* b) {
    asm volatile(
        "mma.sync.aligned.m16n8k16.row.col.f32.bf16.bf16.f32 "
        "{%0,%1,%2,%3}, {%4,%5,%6,%7}, {%8,%9}, {%0,%1,%2,%3};"
        : "+f"(c[0]), "+f"(c[1]), "+f"(c[2]), "+f"(c[3])
        : "r"(a[0]), "r"(a[1]), "r"(a[2]), "r"(a[3]),
          "r"(b[0]), "r"(b[1]));
}

// split fp32x4 -> bf16 hi x4 (8B) + lo x4 (8B)
__device__ __forceinline__ void split_store(__nv_bfloat16* hi_p,
                                            __nv_bfloat16* lo_p, float4 v) {
    __nv_bfloat162 h0 = __floats2bfloat162_rn(v.x, v.y);
    __nv_bfloat162 h1 = __floats2bfloat162_rn(v.z, v.w);
    float2 f0 = __bfloat1622float2(h0);
    float2 f1 = __bfloat1622float2(h1);
    __nv_bfloat162 l0 = __floats2bfloat162_rn(v.x - f0.x, v.y - f0.y);
    __nv_bfloat162 l1 = __floats2bfloat162_rn(v.z - f1.x, v.w - f1.y);
    uint2 hu, lu;
    hu.x = *(uint32_t*)&h0; hu.y = *(uint32_t*)&h1;
    lu.x = *(uint32_t*)&l0; lu.y = *(uint32_t*)&l1;
    *(uint2*)hi_p = hu;
    *(uint2*)lo_p = lu;
}

// ---------------------------------------------------------------------------
// Pipelined tensor-core fused GEMM (mma.sync bf16, split-3):
//   C[M,N] = A1[M,K]@W1[N,K]^T (+ A2@W2^T) (+ bias) (+ addend) [relu]
// CTA tile 128x128, BK=32 fp32 k per chunk, 8 warps 4(m)x2(n), warp 32x64.
// Next chunk prefetched to registers during MMA; smem double-buffered.
// ---------------------------------------------------------------------------
#define LDT 40
#define TILE_ELEMS   (128 * LDT)           // per tile (bf16)
#define BUF_ELEMS    (4 * TILE_ELEMS)      // Ah, Al, Bh, Bl
#define SMEM_PIPE_B  (2 * BUF_ELEMS * 2)   // 2 buffers, bytes = 81920

__device__ __forceinline__ void prefetch_tiles(
    const float* __restrict__ A, const float* __restrict__ W,
    int bm, int bn, int M, int K, int k0, int tid,
    float4* pa, float4* pb)
{
#pragma unroll
    for (int i = 0; i < 4; i++) {
        int u  = tid + i * 256;
        int m  = u >> 3;
        int k4 = (u & 7) * 4;
        int gr = bm + m;
        pa[i] = (gr < M) ? *(const float4*)(A + (size_t)gr * K + k0 + k4)
                         : make_float4(0.f, 0.f, 0.f, 0.f);
        pb[i] = *(const float4*)(W + (size_t)(bn + m) * K + k0 + k4);
    }
}

__global__ void __launch_bounds__(256) gemm_mma_kernel(
    const float* __restrict__ A1, const float* __restrict__ W1,
    const float* __restrict__ bias,
    const float* __restrict__ A2, const float* __restrict__ W2,
    const float* __restrict__ addend,
    float* __restrict__ C, int M, int N, int K, int do_relu)
{
    extern __shared__ __align__(16) __nv_bfloat16 smbuf[];

    const int tid    = threadIdx.x;
    const int lane   = tid & 31;
    const int wid    = tid >> 5;
    const int warp_m = wid & 3;
    const int warp_n = wid >> 2;
    const int bm     = blockIdx.x * 128;
    const int bn     = blockIdx.y * 128;

    float acc[2][8][4];
#pragma unroll
    for (int f = 0; f < 2; f++)
#pragma unroll
        for (int j = 0; j < 8; j++)
#pragma unroll
            for (int q = 0; q < 4; q++) acc[f][j][q] = 0.0f;

    const int a_r = lane & 15;
    const int a_c = (lane >> 4) * 8;
    const int b_r = (lane & 7) + ((lane >> 4) & 1) * 8;
    const int b_c = ((lane >> 3) & 1) * 8;

    const int cpp   = K / 32;                    // chunks per pass
    const int npass = (A2 != nullptr) ? 2 : 1;
    const int nch   = npass * cpp;

    // per-thread STS coordinates
    const int st_m  = tid >> 3;        // row handled in loads (with +128 stride)
    const int st_k4 = (tid & 7) * 4;

    float4 pa[4], pb[4];
    prefetch_tiles(A1, W1, bm, bn, M, K, 0, tid, pa, pb);

    const uint32_t smbase = smem_u32(smbuf);

    for (int c = 0; c < nch; c++) {
        __nv_bfloat16* buf = smbuf + (c & 1) * BUF_ELEMS;
        __nv_bfloat16* Ah = buf;
        __nv_bfloat16* Al = buf + TILE_ELEMS;
        __nv_bfloat16* Bh = buf + 2 * TILE_ELEMS;
        __nv_bfloat16* Bl = buf + 3 * TILE_ELEMS;

        // store prefetched regs to smem (bf16 hi/lo split)
#pragma unroll
        for (int i = 0; i < 4; i++) {
            int m = st_m + i * 32;
            split_store(&Ah[m * LDT + st_k4], &Al[m * LDT + st_k4], pa[i]);
            split_store(&Bh[m * LDT + st_k4], &Bl[m * LDT + st_k4], pb[i]);
        }
        __syncthreads();

        // prefetch next chunk (overlaps with MMA below)
        if (c + 1 < nch) {
            int cn   = c + 1;
            int pass = cn / cpp;
            int k0   = (cn - pass * cpp) * 32;
            prefetch_tiles(pass ? A2 : A1, pass ? W2 : W1,
                           bm, bn, M, K, k0, tid, pa, pb);
        }

        const uint32_t sAh = smbase + (uint32_t)((c & 1) * BUF_ELEMS) * 2;
        const uint32_t sAl = sAh + TILE_ELEMS * 2;
        const uint32_t sBh = sAh + 2 * TILE_ELEMS * 2;
        const uint32_t sBl = sAh + 3 * TILE_ELEMS * 2;

#pragma unroll
        for (int ks = 0; ks < 32; ks += 16) {
            uint32_t ah[8], bx[16];

#pragma unroll
            for (int f = 0; f < 2; f++) {
                int row = warp_m * 32 + f * 16 + a_r;
                ldsm4(&ah[4 * f], sAh + (uint32_t)(row * LDT + ks + a_c) * 2);
            }
#pragma unroll
            for (int g = 0; g < 4; g++) {
                int row = warp_n * 64 + g * 16 + b_r;
                ldsm4(&bx[4 * g], sBh + (uint32_t)(row * LDT + ks + b_c) * 2);
            }
            // hh
#pragma unroll
            for (int f = 0; f < 2; f++)
#pragma unroll
                for (int j = 0; j < 8; j++)
                    mma_bf16(acc[f][j], &ah[4 * f], &bx[2 * j]);

            // lh: al x bh
            {
                uint32_t al[8];
#pragma unroll
                for (int f = 0; f < 2; f++) {
                    int row = warp_m * 32 + f * 16 + a_r;
                    ldsm4(&al[4 * f],
                          sAl + (uint32_t)(row * LDT + ks + a_c) * 2);
                }
#pragma unroll
                for (int f = 0; f < 2; f++)
#pragma unroll
                    for (int j = 0; j < 8; j++)
                        mma_bf16(acc[f][j], &al[4 * f], &bx[2 * j]);
            }
            // hl: ah x bl (overwrite bx)
#pragma unroll
            for (int g = 0; g < 4; g++) {
                int row = warp_n * 64 + g * 16 + b_r;
                ldsm4(&bx[4 * g], sBl + (uint32_t)(row * LDT + ks + b_c) * 2);
            }
#pragma unroll
            for (int f = 0; f < 2; f++)
#pragma unroll
                for (int j = 0; j < 8; j++)
                    mma_bf16(acc[f][j], &ah[4 * f], &bx[2 * j]);
        }
        // no trailing barrier: next iteration writes the other buffer
    }

    // ---- epilogue ----
#pragma unroll
    for (int f = 0; f < 2; f++) {
        int r0 = warp_m * 32 + f * 16 + (lane >> 2);
#pragma unroll
        for (int half = 0; half < 2; half++) {
            int gr = bm + r0 + half * 8;
            if (gr >= M) continue;
            float* crow = C + (size_t)gr * N;
            const float* arow = addend ? addend + (size_t)gr * N : nullptr;
#pragma unroll
            for (int j = 0; j < 8; j++) {
                int col = bn + warp_n * 64 + j * 8 + (lane & 3) * 2;
                float2 v;
                v.x = acc[f][j][half * 2 + 0];
                v.y = acc[f][j][half * 2 + 1];
                if (bias) {
                    float2 b = *(const float2*)(bias + col);
                    v.x += b.x; v.y += b.y;
                }
                if (arow) {
                    float2 a = *(const float2*)(arow + col);
                    v.x += a.x; v.y += a.y;
                }
                if (do_relu) {
                    v.x = fmaxf(v.x, 0.f);
                    v.y = fmaxf(v.y, 0.f);
                }
                *(float2*)(crow + col) = v;
            }
        }
    }
}

// ---------------------------------------------------------------------------
// Edge scatter-add, F=128:  agg[sidx[e]] += x[gidx[e]]  (red.global.add.v4)
// ---------------------------------------------------------------------------
__global__ void __launch_bounds__(256) scatter_add128_kernel(
    const float* __restrict__ x,
    const int* __restrict__ gidx,
    const int* __restrict__ sidx,
    float* __restrict__ agg, int E)
{
    long long idx = (long long)blockIdx.x * blockDim.x + threadIdx.x;
    if (idx >= (long long)E * 32) return;
    int e = (int)(idx >> 5);
    int c = (int)(idx & 31) * 4;

    int g = __ldg(gidx + e);
    int s = __ldg(sidx + e);
    float4 v = *(const float4*)(x + (size_t)g * 128 + c);
    float* p = agg + (size_t)s * 128 + c;
    asm volatile("red.global.add.v4.f32 [%0], {%1, %2, %3, %4};"
                 :: "l"(p), "f"(v.x), "f"(v.y), "f"(v.z), "f"(v.w)
                 : "memory");
}

// ---------------------------------------------------------------------------

extern "C" void kernel_launch(void* const* d_in, const int* in_sizes, int n_in,
                              void* d_out, int out_size)
{
    const float* x_user       = (const float*)d_in[0];
    const float* x_issue      = (const float*)d_in[1];
    const float* W_mlp        = (const float*)d_in[2];
    const float* b_mlp        = (const float*)d_in[3];
    const float* c1_ui_rel_W  = (const float*)d_in[4];
    const float* c1_ui_rel_b  = (const float*)d_in[5];
    const float* c1_ui_root_W = (const float*)d_in[6];
    const float* c1_iu_rel_W  = (const float*)d_in[7];
    const float* c1_iu_rel_b  = (const float*)d_in[8];
    const float* c1_iu_root_W = (const float*)d_in[9];
    const float* c2_ui_rel_W  = (const float*)d_in[10];
    const float* c2_ui_rel_b  = (const float*)d_in[11];
    const float* c2_ui_root_W = (const float*)d_in[12];
    const float* c2_iu_rel_W  = (const float*)d_in[13];
    const float* c2_iu_rel_b  = (const float*)d_in[14];
    const float* c2_iu_root_W = (const float*)d_in[15];
    const int*   src          = (const int*)d_in[16];
    const int*   dst          = (const int*)d_in[17];

    float* out       = (float*)d_out;
    float* out_issue = out;
    float* out_user  = out + (size_t)NI * DOUT;

    float* S = nullptr;
    cudaGetSymbolAddress((void**)&S, g_scratch);
    float* xi    = S + OFF_XI;
    float* agg_i = S + OFF_AGG_I;
    float* agg_u = S + OFF_AGG_U;
    float* h_i   = S + OFF_H_I;
    float* h_u   = S + OFF_H_U;
    float* y_u2  = S + OFF_Y_U2;
    float* y_i2  = S + OFF_Y_I2;

    cudaFuncSetAttribute(gemm_mma_kernel,
                         cudaFuncAttributeMaxDynamicSharedMemorySize,
                         SMEM_PIPE_B);

    // zero conv1 aggregation buffers (contiguous: agg_i then agg_u)
    cudaMemsetAsync(agg_i, 0,
                    ((size_t)NI + NU) * DIN * sizeof(float), 0);

    dim3 blk(256);
    const int snb = (int)(((long long)NE * 32 + 255) / 256);
    const int gNI = (NI + 127) / 128;
    const int gNU = (NU + 127) / 128;

    // xi = x_issue @ W_mlp^T + b_mlp      (M=NI, N=128, K=128)
    gemm_mma_kernel<<<dim3(gNI, 1), blk, SMEM_PIPE_B>>>(
        x_issue, W_mlp, b_mlp, nullptr, nullptr, nullptr,
        xi, NI, DIN, DIN, 0);

    // conv1 scatters (F=128)
    scatter_add128_kernel<<<snb, blk>>>(x_user, src, dst, agg_i, NE);
    scatter_add128_kernel<<<snb, blk>>>(xi,     dst, src, agg_u, NE);

    // h_i = relu(agg_i@c1_ui_rel^T + b + xi@c1_ui_root^T)  (N=256, K=128 x2)
    gemm_mma_kernel<<<dim3(gNI, 2), blk, SMEM_PIPE_B>>>(
        agg_i, c1_ui_rel_W, c1_ui_rel_b, xi, c1_ui_root_W, nullptr,
        h_i, NI, DHID, DIN, 1);
    // h_u = relu(agg_u@c1_iu_rel^T + b + x_user@c1_iu_root^T)
    gemm_mma_kernel<<<dim3(gNU, 2), blk, SMEM_PIPE_B>>>(
        agg_u, c1_iu_rel_W, c1_iu_rel_b, x_user, c1_iu_root_W, nullptr,
        h_u, NU, DHID, DIN, 1);

    // conv2 rel: transform-before-scatter (N=128, K=256)
    gemm_mma_kernel<<<dim3(gNU, 1), blk, SMEM_PIPE_B>>>(
        h_u, c2_ui_rel_W, nullptr, nullptr, nullptr, nullptr,
        y_u2, NU, DOUT, DHID, 0);
    gemm_mma_kernel<<<dim3(gNI, 1), blk, SMEM_PIPE_B>>>(
        h_i, c2_iu_rel_W, nullptr, nullptr, nullptr, nullptr,
        y_i2, NI, DOUT, DHID, 0);

    // conv2 root GEMMs write d_out directly (bias included)
    gemm_mma_kernel<<<dim3(gNI, 1), blk, SMEM_PIPE_B>>>(
        h_i, c2_ui_root_W, c2_ui_rel_b, nullptr, nullptr, nullptr,
        out_issue, NI, DOUT, DHID, 0);
    gemm_mma_kernel<<<dim3(gNU, 1), blk, SMEM_PIPE_B>>>(
        h_u, c2_iu_root_W, c2_iu_rel_b, nullptr, nullptr, nullptr,
        out_user, NU, DOUT, DHID, 0);

    // conv2 scatters add edge messages directly into the outputs
    scatter_add128_kernel<<<snb, blk>>>(y_u2, src, dst, out_issue, NE);
    scatter_add128_kernel<<<snb, blk>>>(y_i2, dst, src, out_user, NE);
}